// round 1
// baseline (speedup 1.0000x reference)
#include <cuda_runtime.h>
#include <math.h>

#define KNB 40
#define DF 128
#define MDIM 384
#define C2 768
#define HH 4
#define DHD 96
#define BB 128
#define N1Q 10240
#define N2Q 256
#define THREADS 320
#define MC 8
#define KVP 772

// ---------------- scratch (__device__ globals, no allocation) ----------------
__device__ float g_WA[2][2][128 * 768];   // fused Wrel@[Wk|Wv] per layer/etype
__device__ float g_WB[2][128 * 768];      // [Wk|Wv] rows 128..255 (edge feat)
__device__ float g_WC[2][128 * 768];      // [Wk|Wv] rows 256..383 (time feat)
__device__ float g_qconst[2][384];
__device__ float g_WoM1[2][384 * 128];    // Wo @ Wm1[:384]
__device__ float g_h1[N1Q * DF];
__device__ float g_h2[N2Q * DF];

// cos with explicit range reduction (args up to ~2000 rad)
__device__ __forceinline__ float fcosr(float x) {
    float n = rintf(x * 0.15915494309189535f);
    float r = fmaf(n, -6.2831855f, x);       // hi part of 2*pi
    r = fmaf(n, 1.7484556e-7f, r);           // lo correction
    return __cosf(r);
}

__device__ __forceinline__ void fma4(float* a, float x, float4 v) {
    a[0] = fmaf(x, v.x, a[0]);
    a[1] = fmaf(x, v.y, a[1]);
    a[2] = fmaf(x, v.z, a[2]);
    a[3] = fmaf(x, v.w, a[3]);
}

// ---------------- precompute: fused K/V weights ----------------
__global__ void pre_weights(const float* __restrict__ Wrel,
                            const float* __restrict__ Wk,
                            const float* __restrict__ Wv) {
    int bid = blockIdx.x;          // 1024 = 2 layers * 4 mats * 128 rows
    int l = bid >> 9;
    int rem = bid & 511;
    int which = rem >> 7;          // 0:WA et0, 1:WA et1, 2:WB, 3:WC
    int m = rem & 127;
    int tid = threadIdx.x;         // 256
    const float* WkL = Wk + l * MDIM * MDIM;
    const float* WvL = Wv + l * MDIM * MDIM;
    if (which < 2) {
        const float* wr = Wrel + ((l * 2 + which) * 128 + m) * 128;
        float* out = &g_WA[l][which][m * C2];
        for (int c = tid; c < C2; c += 256) {
            const float* wsrc = (c < 384) ? (WkL + c) : (WvL + (c - 384));
            float acc = 0.f;
            for (int j = 0; j < 128; j++) acc = fmaf(wr[j], wsrc[j * MDIM], acc);
            out[c] = acc;
        }
    } else {
        int roff = (which == 2) ? 128 : 256;
        float* out = (which == 2) ? &g_WB[l][m * C2] : &g_WC[l][m * C2];
        for (int c = tid; c < C2; c += 256) {
            out[c] = (c < 384) ? WkL[(roff + m) * MDIM + c]
                               : WvL[(roff + m) * MDIM + (c - 384)];
        }
    }
}

// ---------------- precompute: qconst + Wo@Wm1 ----------------
__global__ void pre_misc(const float* __restrict__ Wq,
                         const float* __restrict__ Wo,
                         const float* __restrict__ Wm1,
                         const float* __restrict__ phase) {
    int bid = blockIdx.x;          // 770 = 2*(384+1)
    int l = bid / 385;
    int r = bid % 385;
    int tid = threadIdx.x;         // 384
    if (r == 384) {
        if (tid < 384) {
            float acc = 0.f;
            for (int j = 0; j < 128; j++)
                acc = fmaf(cosf(phase[j]), Wq[l * MDIM * MDIM + (256 + j) * MDIM + tid], acc);
            g_qconst[l][tid] = acc;
        }
    } else {
        if (tid < 128) {
            float acc = 0.f;
            for (int j = 0; j < MDIM; j++)
                acc = fmaf(Wo[l * MDIM * MDIM + r * MDIM + j],
                           Wm1[(l * 512 + j) * 128 + tid], acc);
            g_WoM1[l][r * 128 + tid] = acc;
        }
    }
}

// ---------------- fused attention layer: one CTA per query node ----------------
__global__ __launch_bounds__(THREADS, 1)
void attn_kernel(int layer,
                 const int* __restrict__ nghNode, const int* __restrict__ nghEidx,
                 const float* __restrict__ nghT, const int* __restrict__ nghEt,
                 const int* __restrict__ srcA, const int* __restrict__ srcB,
                 const float* __restrict__ srcTime,
                 const float* __restrict__ n_feat, const float* __restrict__ e_feat,
                 const float* __restrict__ mem_tab,
                 const float* __restrict__ freq, const float* __restrict__ phase,
                 const float* __restrict__ Wq, const float* __restrict__ Wm1,
                 const float* __restrict__ bm1, const float* __restrict__ Wm2,
                 const float* __restrict__ bm2) {
    extern __shared__ float sm[];
    float* sSRC = sm;                 // 128
    float* sQ   = sm + 128;           // 384
    float* sS   = sm + 512;           // 160
    float* sO   = sm + 672;           // 384
    float* sR   = sm + 1056;          // 128
    int*   sRawEt  = (int*)(sm + 1184);
    int*   sRawNid = (int*)(sm + 1224);
    int*   sRawEid = (int*)(sm + 1264);
    float* sRawT   = sm + 1304;
    int*   sEt   = (int*)(sm + 1344);
    int*   sMask = (int*)(sm + 1384);
    int*   sNid  = (int*)(sm + 1424);
    int*   sEid  = (int*)(sm + 1464);
    float* sDt   = sm + 1504;
    int*   sPerm = (int*)(sm + 1544); // -> 1584
    float* sNF  = sm + 1600;          // 40*128
    float* sEF  = sNF + KNB * DF;
    float* sTF  = sEF + KNB * DF;
    float* sWS  = sm + 1600 + 3 * KNB * DF;   // 4*MC*768
    float* sKVH = sm + 1600;          // 40*772 (overlays NF/EF/TF + part of WS)

    const int n = blockIdx.x;
    const int tid = threadIdx.x;

    // ---- P0: meta + src feature ----
    if (tid < KNB) {
        sRawNid[tid] = nghNode[n * KNB + tid];
        sRawEid[tid] = nghEidx[n * KNB + tid];
        sRawT[tid]   = nghT[n * KNB + tid];
        sRawEt[tid]  = nghEt[n * KNB + tid];
    }
    int srcId;
    float srcT;
    if (layer == 0) { srcId = srcA[n]; srcT = srcTime[n]; }
    else { srcId = (n < BB) ? srcA[n] : srcB[n - BB]; srcT = srcTime[n & (BB - 1)]; }
    if (tid < DF) sSRC[tid] = n_feat[srcId * DF + tid] + mem_tab[srcId * DF + tid];
    __syncthreads();
    if (tid == 0) {   // stable partition by etype -> warp-uniform A matrix
        int c = 0;
        for (int k = 0; k < KNB; k++) if (sRawEt[k] == 0) sPerm[c++] = k;
        for (int k = 0; k < KNB; k++) if (sRawEt[k] != 0) sPerm[c++] = k;
    }
    __syncthreads();
    if (tid < KNB) {
        int k = sPerm[tid];
        sEt[tid]   = sRawEt[k];
        sNid[tid]  = sRawNid[k];
        sEid[tid]  = sRawEid[k];
        sDt[tid]   = srcT - sRawT[k];
        sMask[tid] = (sRawNid[k] == 0) ? 1 : 0;
    }
    __syncthreads();

    // ---- Pq: q projection (src part + qconst) ----
    for (int c = tid; c < MDIM; c += THREADS) {
        float acc = g_qconst[layer][c];
        const float* wq = Wq + layer * MDIM * MDIM + c;
        for (int m = 0; m < DF; m++) acc = fmaf(sSRC[m], wq[m * MDIM], acc);
        sQ[c] = acc;
    }

    // ---- P1: stage neighbor features (sorted order) ----
    for (int i = tid; i < KNB * DF; i += THREADS) {
        int row = i >> 7, j = i & 127;
        float nf;
        if (layer == 0) {
            int id = sNid[row];
            nf = n_feat[id * DF + j] + mem_tab[id * DF + j];
        } else {
            nf = g_h1[(n * KNB + sPerm[row]) * DF + j];
        }
        sNF[row * DF + j] = nf;
        sEF[row * DF + j] = e_feat[sEid[row] * DF + j];
        sTF[row * DF + j] = fcosr(fmaf(sDt[row], freq[j], phase[j]));
    }

    // ---- P2: fused K/V GEMM: 4 rows x 24 cols per thread ----
    float acc[4][24];
#pragma unroll
    for (int rr = 0; rr < 4; rr++)
#pragma unroll
        for (int q = 0; q < 24; q++) acc[rr][q] = 0.f;

    const int rg = tid >> 5, cg = tid & 31;
    const int r0 = rg * 4;
    const int et0 = sEt[r0];
    int etr[4];
#pragma unroll
    for (int rr = 0; rr < 4; rr++) etr[rr] = sEt[r0 + rr];
    const bool uni = (et0 == sEt[r0 + 3]);

    const float* gW0 = &g_WA[layer][0][0];
    const float* gW1 = &g_WA[layer][1][0];
    const float* gW2 = &g_WB[layer][0];
    const float* gW3 = &g_WC[layer][0];

#pragma unroll 1
    for (int m0 = 0; m0 < DF; m0 += MC) {
        __syncthreads();
#pragma unroll 1
        for (int i = tid; i < 4 * MC * 192; i += THREADS) {
            int mat = i / (MC * 192);
            int rem = i - mat * (MC * 192);
            int mm = rem / 192;
            int c4 = rem - mm * 192;
            const float* src = (mat == 0) ? gW0 : (mat == 1) ? gW1 : (mat == 2) ? gW2 : gW3;
            ((float4*)sWS)[i] = ((const float4*)(src + (m0 + mm) * C2))[c4];
        }
        __syncthreads();
#pragma unroll 1
        for (int mm = 0; mm < MC; mm++) {
            const int m = m0 + mm;
            float xn[4], xe[4], xt[4];
#pragma unroll
            for (int rr = 0; rr < 4; rr++) {
                xn[rr] = sNF[(r0 + rr) * DF + m];
                xe[rr] = sEF[(r0 + rr) * DF + m];
                xt[rr] = sTF[(r0 + rr) * DF + m];
            }
            const float* wbb = sWS + (2 * MC + mm) * C2 + cg * 4;
            const float* wcc = sWS + (3 * MC + mm) * C2 + cg * 4;
            if (uni) {
                const float* waa = sWS + (et0 * MC + mm) * C2 + cg * 4;
#pragma unroll
                for (int j = 0; j < 6; j++) {
                    float4 a4 = *(const float4*)(waa + j * 128);
                    float4 b4 = *(const float4*)(wbb + j * 128);
                    float4 c4 = *(const float4*)(wcc + j * 128);
#pragma unroll
                    for (int rr = 0; rr < 4; rr++) {
                        fma4(&acc[rr][j * 4], xn[rr], a4);
                        fma4(&acc[rr][j * 4], xe[rr], b4);
                        fma4(&acc[rr][j * 4], xt[rr], c4);
                    }
                }
            } else {
#pragma unroll
                for (int j = 0; j < 6; j++) {
                    float4 b4 = *(const float4*)(wbb + j * 128);
                    float4 c4 = *(const float4*)(wcc + j * 128);
#pragma unroll
                    for (int rr = 0; rr < 4; rr++) {
                        float4 a4 = *(const float4*)(sWS + (etr[rr] * MC + mm) * C2 + cg * 4 + j * 128);
                        fma4(&acc[rr][j * 4], xn[rr], a4);
                        fma4(&acc[rr][j * 4], xe[rr], b4);
                        fma4(&acc[rr][j * 4], xt[rr], c4);
                    }
                }
            }
        }
    }
    __syncthreads();   // all reads of sWS/sNF done before KVH overlay store
#pragma unroll
    for (int rr = 0; rr < 4; rr++) {
#pragma unroll
        for (int j = 0; j < 6; j++) {
            float4 v = make_float4(acc[rr][j * 4], acc[rr][j * 4 + 1],
                                   acc[rr][j * 4 + 2], acc[rr][j * 4 + 3]);
            *(float4*)(sKVH + (r0 + rr) * KVP + cg * 4 + j * 128) = v;
        }
    }
    __syncthreads();

    // ---- P4: attention ----
    if (tid < HH * KNB) {
        int h = tid / KNB, row = tid % KNB;
        const float* kr = sKVH + row * KVP + h * DHD;
        const float* qk = sQ + h * DHD;
        float s = 0.f;
        for (int d = 0; d < DHD; d++) s = fmaf(qk[d], kr[d], s);
        s *= 0.10206207261596577f;   // 1/sqrt(96)
        if (sMask[row]) s = -1000000000.0f;
        sS[h * KNB + row] = s;
    }
    __syncthreads();
    if (tid < HH) {
        float mx = -INFINITY;
        for (int k = 0; k < KNB; k++) mx = fmaxf(mx, sS[tid * KNB + k]);
        float sum = 0.f;
        for (int k = 0; k < KNB; k++) {
            float e = expf(sS[tid * KNB + k] - mx);
            sS[tid * KNB + k] = e;
            sum += e;
        }
        float inv = 1.f / sum;
        for (int k = 0; k < KNB; k++) sS[tid * KNB + k] *= inv;
    }
    __syncthreads();
    for (int c = tid; c < MDIM; c += THREADS) {
        int h = c / DHD;
        float o = 0.f;
        for (int k = 0; k < KNB; k++)
            o = fmaf(sS[h * KNB + k], sKVH[k * KVP + MDIM + c], o);
        sO[c] = o;
    }
    __syncthreads();

    // ---- P5: output MLP (Wo fused into WoM1) ----
    if (tid < DF) {
        float a1 = bm1[layer * DF + tid];
        const float* w1 = &g_WoM1[layer][tid];
        for (int i = 0; i < MDIM; i++) a1 = fmaf(sO[i], w1[i * DF], a1);
        const float* w1b = Wm1 + (layer * 512 + MDIM) * DF + tid;
        for (int m = 0; m < DF; m++) a1 = fmaf(sSRC[m], w1b[m * DF], a1);
        sR[tid] = fmaxf(a1, 0.f);
    }
    __syncthreads();
    if (tid < DF) {
        float a2 = bm2[layer * DF + tid];
        const float* w2 = Wm2 + layer * DF * DF + tid;
        for (int d = 0; d < DF; d++) a2 = fmaf(sR[d], w2[d * DF], a2);
        float* hout = (layer == 0) ? g_h1 : g_h2;
        hout[n * DF + tid] = a2;
    }
}

// ---------------- final bilinear score + sigmoid ----------------
__global__ void final_kernel(const int* __restrict__ etype_l,
                             const float* __restrict__ Wmatch,
                             const float* __restrict__ bmatch,
                             float* __restrict__ out) {
    __shared__ float ste[128];
    __shared__ float red[128];
    int b = blockIdx.x, d = threadIdx.x;
    int et = etype_l[b];
    ste[d] = g_h2[(BB + b) * DF + d];
    __syncthreads();
    float se = g_h2[b * DF + d];
    const float* wm = Wmatch + (et * DF + d) * DF;
    float v = 0.f;
    for (int e = 0; e < DF; e++) v = fmaf(wm[e], ste[e], v);
    red[d] = se * v;
    __syncthreads();
    for (int s = 64; s > 0; s >>= 1) {
        if (d < s) red[d] += red[d + s];
        __syncthreads();
    }
    if (d == 0) {
        float score = red[0] + bmatch[et];
        out[b] = 1.f / (1.f + expf(-score));
    }
}

extern "C" void kernel_launch(void* const* d_in, const int* in_sizes, int n_in,
                              void* d_out, int out_size) {
    const int*   src_idx   = (const int*)d_in[0];
    const int*   tgt_idx   = (const int*)d_in[1];
    const float* cut_time  = (const float*)d_in[2];
    const int*   etype_l   = (const int*)d_in[5];
    const int*   ngh_node2 = (const int*)d_in[6];
    const int*   ngh_eidx2 = (const int*)d_in[7];
    const float* ngh_t2    = (const float*)d_in[8];
    const int*   ngh_et2   = (const int*)d_in[9];
    const int*   ngh_node1 = (const int*)d_in[11];
    const int*   ngh_eidx1 = (const int*)d_in[12];
    const float* ngh_t1    = (const float*)d_in[13];
    const int*   ngh_et1   = (const int*)d_in[14];
    const float* n_feat    = (const float*)d_in[16];
    const float* e_feat    = (const float*)d_in[17];
    const float* mem_tab   = (const float*)d_in[18];
    const float* freq      = (const float*)d_in[19];
    const float* phase     = (const float*)d_in[20];
    const float* Wq        = (const float*)d_in[21];
    const float* Wk        = (const float*)d_in[22];
    const float* Wv        = (const float*)d_in[23];
    const float* Wo        = (const float*)d_in[24];
    const float* Wm1       = (const float*)d_in[25];
    const float* bm1       = (const float*)d_in[26];
    const float* Wm2       = (const float*)d_in[27];
    const float* bm2       = (const float*)d_in[28];
    const float* Wrel      = (const float*)d_in[29];
    const float* Wmatch    = (const float*)d_in[30];
    const float* bmatch    = (const float*)d_in[31];
    float* out = (float*)d_out;

    const int SMEM_BYTES = 41536 * 4;   // 162.25 KB dynamic
    cudaFuncSetAttribute(attn_kernel, cudaFuncAttributeMaxDynamicSharedMemorySize, SMEM_BYTES);

    pre_weights<<<1024, 256>>>(Wrel, Wk, Wv);
    pre_misc<<<770, 384>>>(Wq, Wo, Wm1, phase);

    // layer 1: 10240 query nodes (neighbors of layer-2 neighbors)
    attn_kernel<<<N1Q, THREADS, SMEM_BYTES>>>(
        0, ngh_node1, ngh_eidx1, ngh_t1, ngh_et1,
        ngh_node2, (const int*)0, ngh_t2,
        n_feat, e_feat, mem_tab, freq, phase, Wq, Wm1, bm1, Wm2, bm2);

    // layer 2: 256 query nodes (src + tgt)
    attn_kernel<<<N2Q, THREADS, SMEM_BYTES>>>(
        1, ngh_node2, ngh_eidx2, ngh_t2, ngh_et2,
        src_idx, tgt_idx, cut_time,
        n_feat, e_feat, mem_tab, freq, phase, Wq, Wm1, bm1, Wm2, bm2);

    final_kernel<<<BB, 128>>>(etype_l, Wmatch, bmatch, out);
}